// round 8
// baseline (speedup 1.0000x reference)
#include <cuda_runtime.h>
#include <cuda_bf16.h>

#define NG 1024
#define DG 128
#define HG 256
#define JCH 8            // j-split factor
#define JW (NG / JCH)    // 128 j per chunk

typedef unsigned long long u64;

// ---- scratch (no allocations allowed) ----
__device__ float g_src[NG * HG];            // X @ W1a^T + b1
__device__ float g_nbr[NG * HG];            // X @ W1b^T
__device__ float g_part[JCH][NG * HG];      // per-j-chunk partials (8MB)
__device__ float g_degp[JCH][NG];           // per-chunk degree partials
__device__ float g_msg[NG * DG];
__device__ float g_gi[NG * 3 * DG];
__device__ float g_gh[NG * 3 * DG];

// ---- packed f32x2 helpers (Blackwell) ----
__device__ __forceinline__ u64 pk2(float lo, float hi) {
    u64 r; asm("mov.b64 %0, {%1, %2};" : "=l"(r) : "f"(lo), "f"(hi)); return r;
}
__device__ __forceinline__ float2 upk(u64 v) {
    float2 r; asm("mov.b64 {%0, %1}, %2;" : "=f"(r.x), "=f"(r.y) : "l"(v)); return r;
}
__device__ __forceinline__ u64 add2(u64 a, u64 b) {
    u64 r; asm("add.rn.f32x2 %0, %1, %2;" : "=l"(r) : "l"(a), "l"(b)); return r;
}
__device__ __forceinline__ void fma2(u64& acc, u64 a, u64 b) {
    asm("fma.rn.f32x2 %0, %1, %2, %0;" : "+l"(acc) : "l"(a), "l"(b));
}

// ============================================================
// R3-proven 64x64x32 GEMM tile body (f32x2 microtile), used by fusedX only.
// ============================================================
__device__ __forceinline__ void gemm_tile(
    float (*As)[64], float (*Bs)[64],
    const float* __restrict__ A, int lda,
    const float* __restrict__ B, int ldb,
    const float* __restrict__ bias,
    float* __restrict__ C, int ldc,
    int K, int row0, int col0)
{
    const int tid = threadIdx.x;
    const int tc = tid & 15;
    const int tr = tid >> 4;

    u64 acc2[4][2];
#pragma unroll
    for (int r = 0; r < 4; ++r) { acc2[r][0] = 0ull; acc2[r][1] = 0ull; }

    for (int k0 = 0; k0 < K; k0 += 32) {
#pragma unroll
        for (int it = 0; it < 2; ++it) {
            int idx = tid + it * 256;          // 0..511
            int r   = idx >> 3;                // 0..63
            int c4  = (idx & 7) * 4;           // 0..28
            float4 va = *(const float4*)(A + (size_t)(row0 + r) * lda + k0 + c4);
            As[c4 + 0][r] = va.x; As[c4 + 1][r] = va.y;
            As[c4 + 2][r] = va.z; As[c4 + 3][r] = va.w;
            float4 vb = *(const float4*)(B + (size_t)(col0 + r) * ldb + k0 + c4);
            Bs[c4 + 0][r] = vb.x; Bs[c4 + 1][r] = vb.y;
            Bs[c4 + 2][r] = vb.z; Bs[c4 + 3][r] = vb.w;
        }
        __syncthreads();
#pragma unroll
        for (int k = 0; k < 32; ++k) {
            float4 a = *(const float4*)&As[k][tr * 4];
            float4 b = *(const float4*)&Bs[k][tc * 4];
            u64 b01 = pk2(b.x, b.y);
            u64 b23 = pk2(b.z, b.w);
            u64 ar;
            ar = pk2(a.x, a.x); fma2(acc2[0][0], ar, b01); fma2(acc2[0][1], ar, b23);
            ar = pk2(a.y, a.y); fma2(acc2[1][0], ar, b01); fma2(acc2[1][1], ar, b23);
            ar = pk2(a.z, a.z); fma2(acc2[2][0], ar, b01); fma2(acc2[2][1], ar, b23);
            ar = pk2(a.w, a.w); fma2(acc2[3][0], ar, b01); fma2(acc2[3][1], ar, b23);
        }
        __syncthreads();
    }

#pragma unroll
    for (int r = 0; r < 4; ++r) {
        int row = row0 + tr * 4 + r;
#pragma unroll
        for (int cp = 0; cp < 2; ++cp) {
            float2 f = upk(acc2[r][cp]);
            int col = col0 + tc * 4 + cp * 2;
            float v0 = f.x, v1 = f.y;
            if (bias) { v0 += bias[col]; v1 += bias[col + 1]; }
            C[(size_t)row * ldc + col]     = v0;
            C[(size_t)row * ldc + col + 1] = v1;
        }
    }
}

// ============================================================
// Fused X-GEMM: src | nbr | gh  (R3-proven). grid (14, 16).
// ============================================================
__global__ __launch_bounds__(256) void gemm_fusedX_kernel(
    const float* __restrict__ X,
    const float* __restrict__ W1,
    const float* __restrict__ b1,
    const float* __restrict__ W_hh,
    const float* __restrict__ b_hh,
    float* __restrict__ src,
    float* __restrict__ nbr,
    float* __restrict__ gh)
{
    __shared__ float As[32][64];
    __shared__ float Bs[32][64];
    const int bx = blockIdx.x;
    const int row0 = blockIdx.y * 64;

    const float* B; int ldb; const float* bias; float* C; int ldc; int col0;
    if (bx < 4)       { B = W1;        ldb = 2 * DG; bias = b1;   C = src; ldc = HG;  col0 = bx * 64; }
    else if (bx < 8)  { B = W1 + DG;   ldb = 2 * DG; bias = 0;    C = nbr; ldc = HG;  col0 = (bx - 4) * 64; }
    else              { B = W_hh;      ldb = DG;     bias = b_hh; C = gh;  ldc = 384; col0 = (bx - 8) * 64; }

    gemm_tile(As, Bs, X, DG, B, ldb, bias, C, ldc, DG, row0, col0);
}

// ============================================================
// part[jb][i,h] = sum_{j in chunk jb} mask[i,j]*relu(src[i,h]+nbr[j,h])
// (exact R3-proven kernel, unchanged)
// ============================================================
__global__ __launch_bounds__(256, 5) void agg_part_kernel(const int* __restrict__ adj)
{
    __shared__ __align__(16) float msh[JW][8];
    const int i0 = blockIdx.x * 8;
    const int jb = blockIdx.y;
    const int j0 = jb * JW;
    const int tid = threadIdx.x;

#pragma unroll
    for (int it = 0; it < 4; ++it) {
        int idx = tid + it * 256;          // 0..1023
        int t = idx >> 7;                  // 0..7
        int j = idx & 127;
        msh[j][t] = (adj[(size_t)(i0 + t) * NG + j0 + j] > 0) ? 1.f : 0.f;
    }
    __syncthreads();

    // degree partials: warp w handles row t=w
    {
        int w = tid >> 5, lane = tid & 31;
        float ds = 0.f;
#pragma unroll
        for (int k = 0; k < 4; ++k) ds += msh[lane + 32 * k][w];
#pragma unroll
        for (int off = 16; off > 0; off >>= 1)
            ds += __shfl_down_sync(0xFFFFFFFFu, ds, off);
        if (lane == 0) g_degp[jb][i0 + w] = ds;
    }

    const int h = tid;
    u64 s2[4], acc2[4];
#pragma unroll
    for (int p = 0; p < 4; ++p) {
        s2[p] = pk2(g_src[(size_t)(i0 + 2 * p) * HG + h],
                    g_src[(size_t)(i0 + 2 * p + 1) * HG + h]);
        acc2[p] = 0ull;
    }
    const float* nb = g_nbr + (size_t)j0 * HG + h;

#pragma unroll 4
    for (int j = 0; j < JW; ++j) {
        float nv = __ldg(nb + (size_t)j * HG);
        u64 nv2 = pk2(nv, nv);
        ulonglong2 ma = *(const ulonglong2*)&msh[j][0];
        ulonglong2 mb = *(const ulonglong2*)&msh[j][4];
        {
            u64 t = add2(s2[0], nv2); float2 f = upk(t);
            f.x = fmaxf(f.x, 0.f); f.y = fmaxf(f.y, 0.f);
            fma2(acc2[0], ma.x, pk2(f.x, f.y));
        }
        {
            u64 t = add2(s2[1], nv2); float2 f = upk(t);
            f.x = fmaxf(f.x, 0.f); f.y = fmaxf(f.y, 0.f);
            fma2(acc2[1], ma.y, pk2(f.x, f.y));
        }
        {
            u64 t = add2(s2[2], nv2); float2 f = upk(t);
            f.x = fmaxf(f.x, 0.f); f.y = fmaxf(f.y, 0.f);
            fma2(acc2[2], mb.x, pk2(f.x, f.y));
        }
        {
            u64 t = add2(s2[3], nv2); float2 f = upk(t);
            f.x = fmaxf(f.x, 0.f); f.y = fmaxf(f.y, 0.f);
            fma2(acc2[3], mb.y, pk2(f.x, f.y));
        }
    }

    float* p = g_part[jb];
#pragma unroll
    for (int t = 0; t < 4; ++t) {
        float2 f = upk(acc2[t]);
        p[(size_t)(i0 + 2 * t) * HG + h]     = f.x;
        p[(size_t)(i0 + 2 * t + 1) * HG + h] = f.y;
    }
}

// ============================================================
// msg kernel (replaces agg_reduce + msg GEMM):
// msg[i,c] = sum_k (sum_s part[s][i,k]) * W2[c,k] + deg[i]*b2[c]
// CTA: 4 rows x 128 cols, 128 threads (thread = col c). grid = 256.
// A rows folded+staged in smem; W2 row read thread-sequentially (L1-resident).
// ============================================================
__global__ __launch_bounds__(128) void msg_kernel(
    const float* __restrict__ W2,
    const float* __restrict__ b2)
{
    __shared__ float rows_sm[4][HG];    // 4KB
    __shared__ float deg_sm[4];
    const int i0 = blockIdx.x * 4;
    const int tid = threadIdx.x;

    // stage: fold 8 partial slabs (ascending s -> deterministic)
#pragma unroll
    for (int it = 0; it < 8; ++it) {
        int idx = tid + it * 128;            // 0..1023
        int t = idx >> 8;                    // 0..3
        int k = idx & 255;
        size_t off = (size_t)(i0 + t) * HG + k;
        float s = g_part[0][off];
#pragma unroll
        for (int c = 1; c < JCH; ++c) s += g_part[c][off];
        rows_sm[t][k] = s;
    }
    if (tid < 4) {
        float d = 0.f;
#pragma unroll
        for (int c = 0; c < JCH; ++c) d += g_degp[c][i0 + tid];
        deg_sm[tid] = d;
    }
    __syncthreads();

    const float* w2row = W2 + (size_t)tid * HG;   // thread-sequential
    u64 acc01 = 0ull, acc23 = 0ull;
#pragma unroll 8
    for (int k = 0; k < HG; ++k) {
        float w = __ldg(w2row + k);
        u64 wp = pk2(w, w);
        fma2(acc01, pk2(rows_sm[0][k], rows_sm[1][k]), wp);
        fma2(acc23, pk2(rows_sm[2][k], rows_sm[3][k]), wp);
    }

    float bv = b2[tid];
    float2 f01 = upk(acc01), f23 = upk(acc23);
    g_msg[(size_t)(i0 + 0) * DG + tid] = fmaf(deg_sm[0], bv, f01.x);
    g_msg[(size_t)(i0 + 1) * DG + tid] = fmaf(deg_sm[1], bv, f01.y);
    g_msg[(size_t)(i0 + 2) * DG + tid] = fmaf(deg_sm[2], bv, f23.x);
    g_msg[(size_t)(i0 + 3) * DG + tid] = fmaf(deg_sm[3], bv, f23.y);
}

// ============================================================
// gi kernel: gi[i,g] = sum_k msg[i,k]*W_ih[g,k] + b_ih[g]
// CTA: 4 rows x 128 cols (col-block), 128 threads. grid = (3, 256).
// ============================================================
__global__ __launch_bounds__(128) void gi_kernel(
    const float* __restrict__ W_ih,
    const float* __restrict__ b_ih)
{
    __shared__ float rows_sm[4][DG];    // 2KB
    const int g = blockIdx.x * 128 + threadIdx.x;   // output col 0..383
    const int i0 = blockIdx.y * 4;
    const int tid = threadIdx.x;

#pragma unroll
    for (int it = 0; it < 4; ++it) {
        int idx = tid + it * 128;            // 0..511
        int t = idx >> 7;                    // 0..3
        int k = idx & 127;
        rows_sm[t][k] = g_msg[(size_t)(i0 + t) * DG + k];
    }
    __syncthreads();

    const float* wrow = W_ih + (size_t)g * DG;     // thread-sequential
    u64 acc01 = 0ull, acc23 = 0ull;
#pragma unroll 8
    for (int k = 0; k < DG; ++k) {
        float w = __ldg(wrow + k);
        u64 wp = pk2(w, w);
        fma2(acc01, pk2(rows_sm[0][k], rows_sm[1][k]), wp);
        fma2(acc23, pk2(rows_sm[2][k], rows_sm[3][k]), wp);
    }

    float bv = b_ih[g];
    float2 f01 = upk(acc01), f23 = upk(acc23);
    g_gi[(size_t)(i0 + 0) * 384 + g] = f01.x + bv;
    g_gi[(size_t)(i0 + 1) * 384 + g] = f01.y + bv;
    g_gi[(size_t)(i0 + 2) * 384 + g] = f23.x + bv;
    g_gi[(size_t)(i0 + 3) * 384 + g] = f23.y + bv;
}

// ============================================================
// GRU elementwise:  out = (1-z)*n + z*h
// ============================================================
__global__ __launch_bounds__(256) void gru_kernel(const float* __restrict__ X,
                                                  float* __restrict__ out)
{
    int idx = blockIdx.x * 256 + threadIdx.x;   // 0..131071
    int i = idx >> 7;
    int d = idx & 127;
    const float* gi = g_gi + (size_t)i * 384;
    const float* gh = g_gh + (size_t)i * 384;
    float r = 1.f / (1.f + __expf(-(gi[d] + gh[d])));
    float z = 1.f / (1.f + __expf(-(gi[128 + d] + gh[128 + d])));
    float n = tanhf(gi[256 + d] + r * gh[256 + d]);
    float hprev = X[idx];
    out[idx] = (1.f - z) * n + z * hprev;
}

// ============================================================
extern "C" void kernel_launch(void* const* d_in, const int* in_sizes, int n_in,
                              void* d_out, int out_size)
{
    (void)in_sizes; (void)n_in; (void)out_size;
    const float* X    = (const float*)d_in[0];   // [1024,128]
    const int*   adj  = (const int*)  d_in[1];   // [1024,1024]
    const float* W1   = (const float*)d_in[2];   // [256,256]
    const float* b1   = (const float*)d_in[3];   // [256]
    const float* W2   = (const float*)d_in[4];   // [128,256]
    const float* b2   = (const float*)d_in[5];   // [128]
    const float* W_ih = (const float*)d_in[6];   // [384,128]
    const float* W_hh = (const float*)d_in[7];   // [384,128]
    const float* b_ih = (const float*)d_in[8];   // [384]
    const float* b_hh = (const float*)d_in[9];   // [384]
    float* out = (float*)d_out;

    float *src, *nbr, *gh;
    cudaGetSymbolAddress((void**)&src, g_src);
    cudaGetSymbolAddress((void**)&nbr, g_nbr);
    cudaGetSymbolAddress((void**)&gh,  g_gh);

    // 1) src | nbr | gh in one launch (224 CTAs) — R3-proven
    gemm_fusedX_kernel<<<dim3(14, NG / 64), 256>>>(X, W1, b1, W_hh, b_hh, src, nbr, gh);
    // 2) masked relu aggregation -> 8 partial slabs + deg partials — R3-proven
    agg_part_kernel<<<dim3(NG / 8, JCH), 256>>>(adj);
    // 3) msg = (fold partials) @ W2^T + deg*b2   (256 CTAs, GEMV-style)
    msg_kernel<<<256, 128>>>(W2, b2);
    // 4) gi = msg @ W_ih^T + b_ih                (768 CTAs, GEMV-style)
    gi_kernel<<<dim3(3, NG / 4), 128>>>(W_ih, b_ih);
    // 5) GRU gates + output
    gru_kernel<<<(NG * DG) / 256, 256>>>(X, out);
}

// round 9
// speedup vs baseline: 1.3966x; 1.3966x over previous
#include <cuda_runtime.h>
#include <cuda_bf16.h>

#define NG 1024
#define DG 128
#define HG 256
#define JCH 8            // j-split factor
#define JW (NG / JCH)    // 128 j per chunk

typedef unsigned long long u64;

// ---- scratch (no allocations allowed) ----
__device__ float g_src[NG * HG];            // X @ W1a^T + b1
__device__ float g_nbr[NG * HG];            // X @ W1b^T
__device__ float g_part[JCH][NG * HG];      // per-j-chunk partials (8MB)
__device__ float g_degp[JCH][NG];           // per-chunk degree partials
__device__ float g_msg[NG * DG];
__device__ float g_gi[NG * 3 * DG];
__device__ float g_gh[NG * 3 * DG];

// ---- packed f32x2 helpers (Blackwell) ----
__device__ __forceinline__ u64 pk2(float lo, float hi) {
    u64 r; asm("mov.b64 %0, {%1, %2};" : "=l"(r) : "f"(lo), "f"(hi)); return r;
}
__device__ __forceinline__ float2 upk(u64 v) {
    float2 r; asm("mov.b64 {%0, %1}, %2;" : "=f"(r.x), "=f"(r.y) : "l"(v)); return r;
}
__device__ __forceinline__ u64 add2(u64 a, u64 b) {
    u64 r; asm("add.rn.f32x2 %0, %1, %2;" : "=l"(r) : "l"(a), "l"(b)); return r;
}
__device__ __forceinline__ void fma2(u64& acc, u64 a, u64 b) {
    asm("fma.rn.f32x2 %0, %1, %2, %0;" : "+l"(acc) : "l"(a), "l"(b));
}

// ============================================================
// R3-proven 64x64x32 GEMM tile body (f32x2 microtile), used by fusedX only.
// ============================================================
__device__ __forceinline__ void gemm_tile(
    float (*As)[64], float (*Bs)[64],
    const float* __restrict__ A, int lda,
    const float* __restrict__ B, int ldb,
    const float* __restrict__ bias,
    float* __restrict__ C, int ldc,
    int K, int row0, int col0)
{
    const int tid = threadIdx.x;
    const int tc = tid & 15;
    const int tr = tid >> 4;

    u64 acc2[4][2];
#pragma unroll
    for (int r = 0; r < 4; ++r) { acc2[r][0] = 0ull; acc2[r][1] = 0ull; }

    for (int k0 = 0; k0 < K; k0 += 32) {
#pragma unroll
        for (int it = 0; it < 2; ++it) {
            int idx = tid + it * 256;          // 0..511
            int r   = idx >> 3;                // 0..63
            int c4  = (idx & 7) * 4;           // 0..28
            float4 va = *(const float4*)(A + (size_t)(row0 + r) * lda + k0 + c4);
            As[c4 + 0][r] = va.x; As[c4 + 1][r] = va.y;
            As[c4 + 2][r] = va.z; As[c4 + 3][r] = va.w;
            float4 vb = *(const float4*)(B + (size_t)(col0 + r) * ldb + k0 + c4);
            Bs[c4 + 0][r] = vb.x; Bs[c4 + 1][r] = vb.y;
            Bs[c4 + 2][r] = vb.z; Bs[c4 + 3][r] = vb.w;
        }
        __syncthreads();
#pragma unroll
        for (int k = 0; k < 32; ++k) {
            float4 a = *(const float4*)&As[k][tr * 4];
            float4 b = *(const float4*)&Bs[k][tc * 4];
            u64 b01 = pk2(b.x, b.y);
            u64 b23 = pk2(b.z, b.w);
            u64 ar;
            ar = pk2(a.x, a.x); fma2(acc2[0][0], ar, b01); fma2(acc2[0][1], ar, b23);
            ar = pk2(a.y, a.y); fma2(acc2[1][0], ar, b01); fma2(acc2[1][1], ar, b23);
            ar = pk2(a.z, a.z); fma2(acc2[2][0], ar, b01); fma2(acc2[2][1], ar, b23);
            ar = pk2(a.w, a.w); fma2(acc2[3][0], ar, b01); fma2(acc2[3][1], ar, b23);
        }
        __syncthreads();
    }

#pragma unroll
    for (int r = 0; r < 4; ++r) {
        int row = row0 + tr * 4 + r;
#pragma unroll
        for (int cp = 0; cp < 2; ++cp) {
            float2 f = upk(acc2[r][cp]);
            int col = col0 + tc * 4 + cp * 2;
            float v0 = f.x, v1 = f.y;
            if (bias) { v0 += bias[col]; v1 += bias[col + 1]; }
            C[(size_t)row * ldc + col]     = v0;
            C[(size_t)row * ldc + col + 1] = v1;
        }
    }
}

// ============================================================
// Fused X-GEMM: src | nbr | gh  (R3-proven). grid (14, 16).
// ============================================================
__global__ __launch_bounds__(256) void gemm_fusedX_kernel(
    const float* __restrict__ X,
    const float* __restrict__ W1,
    const float* __restrict__ b1,
    const float* __restrict__ W_hh,
    const float* __restrict__ b_hh,
    float* __restrict__ src,
    float* __restrict__ nbr,
    float* __restrict__ gh)
{
    __shared__ float As[32][64];
    __shared__ float Bs[32][64];
    const int bx = blockIdx.x;
    const int row0 = blockIdx.y * 64;

    const float* B; int ldb; const float* bias; float* C; int ldc; int col0;
    if (bx < 4)       { B = W1;        ldb = 2 * DG; bias = b1;   C = src; ldc = HG;  col0 = bx * 64; }
    else if (bx < 8)  { B = W1 + DG;   ldb = 2 * DG; bias = 0;    C = nbr; ldc = HG;  col0 = (bx - 4) * 64; }
    else              { B = W_hh;      ldb = DG;     bias = b_hh; C = gh;  ldc = 384; col0 = (bx - 8) * 64; }

    gemm_tile(As, Bs, X, DG, B, ldb, bias, C, ldc, DG, row0, col0);
}

// ============================================================
// part[jb][i,h] = sum_{j in chunk jb} mask[i,j]*relu(src[i,h]+nbr[j,h])
// (exact R3-proven kernel, unchanged)
// ============================================================
__global__ __launch_bounds__(256, 5) void agg_part_kernel(const int* __restrict__ adj)
{
    __shared__ __align__(16) float msh[JW][8];
    const int i0 = blockIdx.x * 8;
    const int jb = blockIdx.y;
    const int j0 = jb * JW;
    const int tid = threadIdx.x;

#pragma unroll
    for (int it = 0; it < 4; ++it) {
        int idx = tid + it * 256;          // 0..1023
        int t = idx >> 7;                  // 0..7
        int j = idx & 127;
        msh[j][t] = (adj[(size_t)(i0 + t) * NG + j0 + j] > 0) ? 1.f : 0.f;
    }
    __syncthreads();

    // degree partials: warp w handles row t=w
    {
        int w = tid >> 5, lane = tid & 31;
        float ds = 0.f;
#pragma unroll
        for (int k = 0; k < 4; ++k) ds += msh[lane + 32 * k][w];
#pragma unroll
        for (int off = 16; off > 0; off >>= 1)
            ds += __shfl_down_sync(0xFFFFFFFFu, ds, off);
        if (lane == 0) g_degp[jb][i0 + w] = ds;
    }

    const int h = tid;
    u64 s2[4], acc2[4];
#pragma unroll
    for (int p = 0; p < 4; ++p) {
        s2[p] = pk2(g_src[(size_t)(i0 + 2 * p) * HG + h],
                    g_src[(size_t)(i0 + 2 * p + 1) * HG + h]);
        acc2[p] = 0ull;
    }
    const float* nb = g_nbr + (size_t)j0 * HG + h;

#pragma unroll 4
    for (int j = 0; j < JW; ++j) {
        float nv = __ldg(nb + (size_t)j * HG);
        u64 nv2 = pk2(nv, nv);
        ulonglong2 ma = *(const ulonglong2*)&msh[j][0];
        ulonglong2 mb = *(const ulonglong2*)&msh[j][4];
        {
            u64 t = add2(s2[0], nv2); float2 f = upk(t);
            f.x = fmaxf(f.x, 0.f); f.y = fmaxf(f.y, 0.f);
            fma2(acc2[0], ma.x, pk2(f.x, f.y));
        }
        {
            u64 t = add2(s2[1], nv2); float2 f = upk(t);
            f.x = fmaxf(f.x, 0.f); f.y = fmaxf(f.y, 0.f);
            fma2(acc2[1], ma.y, pk2(f.x, f.y));
        }
        {
            u64 t = add2(s2[2], nv2); float2 f = upk(t);
            f.x = fmaxf(f.x, 0.f); f.y = fmaxf(f.y, 0.f);
            fma2(acc2[2], mb.x, pk2(f.x, f.y));
        }
        {
            u64 t = add2(s2[3], nv2); float2 f = upk(t);
            f.x = fmaxf(f.x, 0.f); f.y = fmaxf(f.y, 0.f);
            fma2(acc2[3], mb.y, pk2(f.x, f.y));
        }
    }

    float* p = g_part[jb];
#pragma unroll
    for (int t = 0; t < 4; ++t) {
        float2 f = upk(acc2[t]);
        p[(size_t)(i0 + 2 * t) * HG + h]     = f.x;
        p[(size_t)(i0 + 2 * t + 1) * HG + h] = f.y;
    }
}

// ============================================================
// msg GEMV (also folds partials + deg): warp owns row i.
// Lane l holds a[4l..4l+3] and a[128+4l..128+4l+3] (coalesced fold of 8 slabs).
// Per col c: coalesced W2[c] float4 loads + butterfly reduce.
// msg[i,c] = dot(aggrow, W2[c]) + deg*b2[c].  grid 128 x 256 thr (8 rows/CTA).
// ============================================================
__global__ __launch_bounds__(256) void msg_gemv_kernel(
    const float* __restrict__ W2,
    const float* __restrict__ b2)
{
    const int w    = threadIdx.x >> 5;
    const int lane = threadIdx.x & 31;
    const int row  = blockIdx.x * 8 + w;
    const size_t roff = (size_t)row * HG;

    // fold A row (ascending slab order -> deterministic)
    float4 alo = ((const float4*)(g_part[0] + roff))[lane];
    float4 ahi = ((const float4*)(g_part[0] + roff))[32 + lane];
#pragma unroll
    for (int s = 1; s < JCH; ++s) {
        float4 v = ((const float4*)(g_part[s] + roff))[lane];
        alo.x += v.x; alo.y += v.y; alo.z += v.z; alo.w += v.w;
        float4 u = ((const float4*)(g_part[s] + roff))[32 + lane];
        ahi.x += u.x; ahi.y += u.y; ahi.z += u.z; ahi.w += u.w;
    }
    float deg = 0.f;
#pragma unroll
    for (int s = 0; s < JCH; ++s) deg += g_degp[s][row];

    float res = 0.f;
#pragma unroll 4
    for (int c = 0; c < DG; ++c) {
        const float* wr = W2 + (size_t)c * HG;
        float4 wlo = *(const float4*)(wr + 4 * lane);
        float4 whi = *(const float4*)(wr + 128 + 4 * lane);
        float s;
        s = alo.x * wlo.x;
        s = fmaf(alo.y, wlo.y, s);
        s = fmaf(alo.z, wlo.z, s);
        s = fmaf(alo.w, wlo.w, s);
        s = fmaf(ahi.x, whi.x, s);
        s = fmaf(ahi.y, whi.y, s);
        s = fmaf(ahi.z, whi.z, s);
        s = fmaf(ahi.w, whi.w, s);
#pragma unroll
        for (int off = 16; off > 0; off >>= 1)
            s += __shfl_xor_sync(0xFFFFFFFFu, s, off);
        if ((c & 31) == lane) res = fmaf(deg, b2[c], s);
        if ((c & 31) == 31)
            g_msg[(size_t)row * DG + (c & ~31) + lane] = res;
    }
}

// ============================================================
// gi GEMV: warp owns row i, col-block of 128. Lane l holds msg[i][4l..4l+3].
// gi[i,c] = dot(msgrow, W_ih[c]) + b_ih[c].  grid (3,128) x 256 thr.
// ============================================================
__global__ __launch_bounds__(256) void gi_gemv_kernel(
    const float* __restrict__ W_ih,
    const float* __restrict__ b_ih)
{
    const int w    = threadIdx.x >> 5;
    const int lane = threadIdx.x & 31;
    const int row  = blockIdx.y * 8 + w;
    const int c0   = blockIdx.x * 128;

    float4 a = ((const float4*)(g_msg + (size_t)row * DG))[lane];

    float res = 0.f;
#pragma unroll 4
    for (int cc = 0; cc < 128; ++cc) {
        int c = c0 + cc;
        float4 wv = *(const float4*)(W_ih + (size_t)c * DG + 4 * lane);
        float s;
        s = a.x * wv.x;
        s = fmaf(a.y, wv.y, s);
        s = fmaf(a.z, wv.z, s);
        s = fmaf(a.w, wv.w, s);
#pragma unroll
        for (int off = 16; off > 0; off >>= 1)
            s += __shfl_xor_sync(0xFFFFFFFFu, s, off);
        if ((cc & 31) == lane) res = s + b_ih[c];
        if ((cc & 31) == 31)
            g_gi[(size_t)row * 384 + c0 + (cc & ~31) + lane] = res;
    }
}

// ============================================================
// GRU elementwise:  out = (1-z)*n + z*h
// ============================================================
__global__ __launch_bounds__(256) void gru_kernel(const float* __restrict__ X,
                                                  float* __restrict__ out)
{
    int idx = blockIdx.x * 256 + threadIdx.x;   // 0..131071
    int i = idx >> 7;
    int d = idx & 127;
    const float* gi = g_gi + (size_t)i * 384;
    const float* gh = g_gh + (size_t)i * 384;
    float r = 1.f / (1.f + __expf(-(gi[d] + gh[d])));
    float z = 1.f / (1.f + __expf(-(gi[128 + d] + gh[128 + d])));
    float n = tanhf(gi[256 + d] + r * gh[256 + d]);
    float hprev = X[idx];
    out[idx] = (1.f - z) * n + z * hprev;
}

// ============================================================
extern "C" void kernel_launch(void* const* d_in, const int* in_sizes, int n_in,
                              void* d_out, int out_size)
{
    (void)in_sizes; (void)n_in; (void)out_size;
    const float* X    = (const float*)d_in[0];   // [1024,128]
    const int*   adj  = (const int*)  d_in[1];   // [1024,1024]
    const float* W1   = (const float*)d_in[2];   // [256,256]
    const float* b1   = (const float*)d_in[3];   // [256]
    const float* W2   = (const float*)d_in[4];   // [128,256]
    const float* b2   = (const float*)d_in[5];   // [128]
    const float* W_ih = (const float*)d_in[6];   // [384,128]
    const float* W_hh = (const float*)d_in[7];   // [384,128]
    const float* b_ih = (const float*)d_in[8];   // [384]
    const float* b_hh = (const float*)d_in[9];   // [384]
    float* out = (float*)d_out;

    float *src, *nbr, *gh;
    cudaGetSymbolAddress((void**)&src, g_src);
    cudaGetSymbolAddress((void**)&nbr, g_nbr);
    cudaGetSymbolAddress((void**)&gh,  g_gh);

    // 1) src | nbr | gh in one launch (224 CTAs) — R3-proven
    gemm_fusedX_kernel<<<dim3(14, NG / 64), 256>>>(X, W1, b1, W_hh, b_hh, src, nbr, gh);
    // 2) masked relu aggregation -> 8 partial slabs + deg partials — R3-proven
    agg_part_kernel<<<dim3(NG / 8, JCH), 256>>>(adj);
    // 3) msg = (fold partials) @ W2^T + deg*b2   (warp-per-row GEMV, coalesced W)
    msg_gemv_kernel<<<NG / 8, 256>>>(W2, b2);
    // 4) gi = msg @ W_ih^T + b_ih                (warp-per-row GEMV, 3 col-blocks)
    gi_gemv_kernel<<<dim3(3, NG / 8), 256>>>(W_ih, b_ih);
    // 5) GRU gates + output
    gru_kernel<<<(NG * DG) / 256, 256>>>(X, out);
}

// round 10
// speedup vs baseline: 2.0000x; 1.4320x over previous
#include <cuda_runtime.h>
#include <cuda_bf16.h>

#define NG 1024
#define DG 128
#define HG 256
#define JCH 8            // j-split factor
#define JW (NG / JCH)    // 128 j per chunk

typedef unsigned long long u64;

// ---- scratch (no allocations allowed) ----
__device__ float g_src[NG * HG];            // X @ W1a^T + b1
__device__ float g_nbr[NG * HG];            // X @ W1b^T
__device__ float g_part[JCH][NG * HG];      // per-j-chunk partials (8MB)
__device__ float g_degp[JCH][NG];           // per-chunk degree partials
__device__ float g_agg[NG * HG];            // folded aggregation
__device__ float g_deg[NG];
__device__ float g_msg[NG * DG];
__device__ float g_gi[NG * 3 * DG];
__device__ float g_gh[NG * 3 * DG];

// ---- packed f32x2 helpers (Blackwell) ----
__device__ __forceinline__ u64 pk2(float lo, float hi) {
    u64 r; asm("mov.b64 %0, {%1, %2};" : "=l"(r) : "f"(lo), "f"(hi)); return r;
}
__device__ __forceinline__ float2 upk(u64 v) {
    float2 r; asm("mov.b64 {%0, %1}, %2;" : "=f"(r.x), "=f"(r.y) : "l"(v)); return r;
}
__device__ __forceinline__ u64 add2(u64 a, u64 b) {
    u64 r; asm("add.rn.f32x2 %0, %1, %2;" : "=l"(r) : "l"(a), "l"(b)); return r;
}
__device__ __forceinline__ void fma2(u64& acc, u64 a, u64 b) {
    asm("fma.rn.f32x2 %0, %1, %2, %0;" : "+l"(acc) : "l"(a), "l"(b));
}

// ============================================================
// R3-proven 64x64x32 GEMM tile body (f32x2 microtile) — fusedX only.
// ============================================================
__device__ __forceinline__ void gemm_tile(
    float (*As)[64], float (*Bs)[64],
    const float* __restrict__ A, int lda,
    const float* __restrict__ B, int ldb,
    const float* __restrict__ bias,
    float* __restrict__ C, int ldc,
    int K, int row0, int col0)
{
    const int tid = threadIdx.x;
    const int tc = tid & 15;
    const int tr = tid >> 4;

    u64 acc2[4][2];
#pragma unroll
    for (int r = 0; r < 4; ++r) { acc2[r][0] = 0ull; acc2[r][1] = 0ull; }

    for (int k0 = 0; k0 < K; k0 += 32) {
#pragma unroll
        for (int it = 0; it < 2; ++it) {
            int idx = tid + it * 256;          // 0..511
            int r   = idx >> 3;                // 0..63
            int c4  = (idx & 7) * 4;           // 0..28
            float4 va = *(const float4*)(A + (size_t)(row0 + r) * lda + k0 + c4);
            As[c4 + 0][r] = va.x; As[c4 + 1][r] = va.y;
            As[c4 + 2][r] = va.z; As[c4 + 3][r] = va.w;
            float4 vb = *(const float4*)(B + (size_t)(col0 + r) * ldb + k0 + c4);
            Bs[c4 + 0][r] = vb.x; Bs[c4 + 1][r] = vb.y;
            Bs[c4 + 2][r] = vb.z; Bs[c4 + 3][r] = vb.w;
        }
        __syncthreads();
#pragma unroll
        for (int k = 0; k < 32; ++k) {
            float4 a = *(const float4*)&As[k][tr * 4];
            float4 b = *(const float4*)&Bs[k][tc * 4];
            u64 b01 = pk2(b.x, b.y);
            u64 b23 = pk2(b.z, b.w);
            u64 ar;
            ar = pk2(a.x, a.x); fma2(acc2[0][0], ar, b01); fma2(acc2[0][1], ar, b23);
            ar = pk2(a.y, a.y); fma2(acc2[1][0], ar, b01); fma2(acc2[1][1], ar, b23);
            ar = pk2(a.z, a.z); fma2(acc2[2][0], ar, b01); fma2(acc2[2][1], ar, b23);
            ar = pk2(a.w, a.w); fma2(acc2[3][0], ar, b01); fma2(acc2[3][1], ar, b23);
        }
        __syncthreads();
    }

#pragma unroll
    for (int r = 0; r < 4; ++r) {
        int row = row0 + tr * 4 + r;
#pragma unroll
        for (int cp = 0; cp < 2; ++cp) {
            float2 f = upk(acc2[r][cp]);
            int col = col0 + tc * 4 + cp * 2;
            float v0 = f.x, v1 = f.y;
            if (bias) { v0 += bias[col]; v1 += bias[col + 1]; }
            C[(size_t)row * ldc + col]     = v0;
            C[(size_t)row * ldc + col + 1] = v1;
        }
    }
}

// ============================================================
// Fused X-GEMM: src | nbr | gh  (R3-proven). grid (14, 16).
// ============================================================
__global__ __launch_bounds__(256) void gemm_fusedX_kernel(
    const float* __restrict__ X,
    const float* __restrict__ W1,
    const float* __restrict__ b1,
    const float* __restrict__ W_hh,
    const float* __restrict__ b_hh,
    float* __restrict__ src,
    float* __restrict__ nbr,
    float* __restrict__ gh)
{
    __shared__ float As[32][64];
    __shared__ float Bs[32][64];
    const int bx = blockIdx.x;
    const int row0 = blockIdx.y * 64;

    const float* B; int ldb; const float* bias; float* C; int ldc; int col0;
    if (bx < 4)       { B = W1;        ldb = 2 * DG; bias = b1;   C = src; ldc = HG;  col0 = bx * 64; }
    else if (bx < 8)  { B = W1 + DG;   ldb = 2 * DG; bias = 0;    C = nbr; ldc = HG;  col0 = (bx - 4) * 64; }
    else              { B = W_hh;      ldb = DG;     bias = b_hh; C = gh;  ldc = 384; col0 = (bx - 8) * 64; }

    gemm_tile(As, Bs, X, DG, B, ldb, bias, C, ldc, DG, row0, col0);
}

// ============================================================
// part[jb][i,h] = sum_{j in chunk jb} mask[i,j]*relu(src[i,h]+nbr[j,h])
// (exact R3-proven kernel, unchanged)
// ============================================================
__global__ __launch_bounds__(256, 5) void agg_part_kernel(const int* __restrict__ adj)
{
    __shared__ __align__(16) float msh[JW][8];
    const int i0 = blockIdx.x * 8;
    const int jb = blockIdx.y;
    const int j0 = jb * JW;
    const int tid = threadIdx.x;

#pragma unroll
    for (int it = 0; it < 4; ++it) {
        int idx = tid + it * 256;          // 0..1023
        int t = idx >> 7;                  // 0..7
        int j = idx & 127;
        msh[j][t] = (adj[(size_t)(i0 + t) * NG + j0 + j] > 0) ? 1.f : 0.f;
    }
    __syncthreads();

    {
        int w = tid >> 5, lane = tid & 31;
        float ds = 0.f;
#pragma unroll
        for (int k = 0; k < 4; ++k) ds += msh[lane + 32 * k][w];
#pragma unroll
        for (int off = 16; off > 0; off >>= 1)
            ds += __shfl_down_sync(0xFFFFFFFFu, ds, off);
        if (lane == 0) g_degp[jb][i0 + w] = ds;
    }

    const int h = tid;
    u64 s2[4], acc2[4];
#pragma unroll
    for (int p = 0; p < 4; ++p) {
        s2[p] = pk2(g_src[(size_t)(i0 + 2 * p) * HG + h],
                    g_src[(size_t)(i0 + 2 * p + 1) * HG + h]);
        acc2[p] = 0ull;
    }
    const float* nb = g_nbr + (size_t)j0 * HG + h;

#pragma unroll 4
    for (int j = 0; j < JW; ++j) {
        float nv = __ldg(nb + (size_t)j * HG);
        u64 nv2 = pk2(nv, nv);
        ulonglong2 ma = *(const ulonglong2*)&msh[j][0];
        ulonglong2 mb = *(const ulonglong2*)&msh[j][4];
        {
            u64 t = add2(s2[0], nv2); float2 f = upk(t);
            f.x = fmaxf(f.x, 0.f); f.y = fmaxf(f.y, 0.f);
            fma2(acc2[0], ma.x, pk2(f.x, f.y));
        }
        {
            u64 t = add2(s2[1], nv2); float2 f = upk(t);
            f.x = fmaxf(f.x, 0.f); f.y = fmaxf(f.y, 0.f);
            fma2(acc2[1], ma.y, pk2(f.x, f.y));
        }
        {
            u64 t = add2(s2[2], nv2); float2 f = upk(t);
            f.x = fmaxf(f.x, 0.f); f.y = fmaxf(f.y, 0.f);
            fma2(acc2[2], mb.x, pk2(f.x, f.y));
        }
        {
            u64 t = add2(s2[3], nv2); float2 f = upk(t);
            f.x = fmaxf(f.x, 0.f); f.y = fmaxf(f.y, 0.f);
            fma2(acc2[3], mb.y, pk2(f.x, f.y));
        }
    }

    float* p = g_part[jb];
#pragma unroll
    for (int t = 0; t < 4; ++t) {
        float2 f = upk(acc2[t]);
        p[(size_t)(i0 + 2 * t) * HG + h]     = f.x;
        p[(size_t)(i0 + 2 * t + 1) * HG + h] = f.y;
    }
}

// ============================================================
// agg = sum over JCH partials (float4); also finalizes deg. (R3-proven)
// ============================================================
__global__ __launch_bounds__(256) void agg_reduce_kernel()
{
    int idx = blockIdx.x * 256 + threadIdx.x;      // over NG*HG/4 = 65536
    float4 s = make_float4(0.f, 0.f, 0.f, 0.f);
#pragma unroll
    for (int c = 0; c < JCH; ++c) {
        float4 v = ((const float4*)g_part[c])[idx];
        s.x += v.x; s.y += v.y; s.z += v.z; s.w += v.w;
    }
    ((float4*)g_agg)[idx] = s;

    if (idx < NG) {
        float d = 0.f;
#pragma unroll
        for (int c = 0; c < JCH; ++c) d += g_degp[c][idx];
        g_deg[idx] = d;
    }
}

// ============================================================
// msg tile kernel: msg = agg @ W2^T + deg*b2.
// CTA: 8 rows x 32 cols, 64 threads. K=256 split across 2 warps (+combine).
// W2 staged transposed [k][33] (odd stride -> conflict-free reads);
// agg rows staged as f32x2 row-pairs [rp][257].
// grid (DG/32, NG/8) = (4, 128).
// ============================================================
__global__ __launch_bounds__(64) void msg_tile_kernel(
    const float* __restrict__ W2,
    const float* __restrict__ b2)
{
    __shared__ float Wsm[HG][33];       // 33,792 B
    __shared__ u64   Apk[4][257];       //  8,224 B
    const int c0 = blockIdx.x * 32;
    const int i0 = blockIdx.y * 8;
    const int tid = threadIdx.x;

    // stage W2 block transposed: Wsm[k][c] = W2[(c0+c)*HG + k]
#pragma unroll
    for (int it = 0; it < 32; ++it) {
        int idx = tid + it * 64;             // 0..2047
        int c  = idx >> 6;                   // 0..31 (constant per it)
        int k4 = (idx & 63) * 4;             // 0..252
        float4 v = *(const float4*)(W2 + (size_t)(c0 + c) * HG + k4);
        Wsm[k4 + 0][c] = v.x; Wsm[k4 + 1][c] = v.y;
        Wsm[k4 + 2][c] = v.z; Wsm[k4 + 3][c] = v.w;
    }
    // stage agg row-pairs
#pragma unroll
    for (int it = 0; it < 16; ++it) {
        int idx = tid + it * 64;             // 0..1023
        int rp = idx >> 8;                   // 0..3
        int k  = idx & 255;
        float lo = g_agg[(size_t)(i0 + 2 * rp)     * HG + k];
        float hi = g_agg[(size_t)(i0 + 2 * rp + 1) * HG + k];
        Apk[rp][k] = pk2(lo, hi);
    }
    __syncthreads();

    const int w    = tid >> 5;               // k-half
    const int lane = tid & 31;
    const int rp   = lane >> 3;              // 0..3 row-pair
    const int cg   = lane & 7;               // 0..7 col group of 4
    const int kb   = w * 128;

    u64 acc[4] = {0ull, 0ull, 0ull, 0ull};
#pragma unroll 4
    for (int kk = 0; kk < 128; ++kk) {
        int k = kb + kk;
        u64 a = Apk[rp][k];
        float w0 = Wsm[k][cg * 4 + 0];
        float w1 = Wsm[k][cg * 4 + 1];
        float w2 = Wsm[k][cg * 4 + 2];
        float w3 = Wsm[k][cg * 4 + 3];
        fma2(acc[0], a, pk2(w0, w0));
        fma2(acc[1], a, pk2(w1, w1));
        fma2(acc[2], a, pk2(w2, w2));
        fma2(acc[3], a, pk2(w3, w3));
    }

    // combine halves (deterministic: acc_w0 + acc_w1), reuse Apk as buffer
    __syncthreads();
    u64* buf = &Apk[0][0];
    if (w == 1) {
#pragma unroll
        for (int q = 0; q < 4; ++q) buf[lane * 4 + q] = acc[q];
    }
    __syncthreads();
    if (w == 0) {
        const int r0 = i0 + 2 * rp;
        const float d0 = g_deg[r0], d1 = g_deg[r0 + 1];
#pragma unroll
        for (int q = 0; q < 4; ++q) {
            u64 s = add2(acc[q], buf[lane * 4 + q]);
            float2 f = upk(s);
            int col = c0 + cg * 4 + q;
            float bv = b2[col];
            g_msg[(size_t)r0 * DG + col]       = fmaf(d0, bv, f.x);
            g_msg[(size_t)(r0 + 1) * DG + col] = fmaf(d1, bv, f.y);
        }
    }
}

// ============================================================
// gi tile kernel: gi = msg @ W_ih^T + b_ih.  K=128.
// CTA: 8 rows x 64 cols, 64 threads; warp w owns col-block w*32 (no combine).
// grid (384/64, NG/8) = (6, 128).
// ============================================================
__global__ __launch_bounds__(64) void gi_tile_kernel(
    const float* __restrict__ W_ih,
    const float* __restrict__ b_ih)
{
    __shared__ float Wsm[DG][65];       // 33,280 B
    __shared__ u64   Apk[4][129];       //  4,128 B
    const int c0 = blockIdx.x * 64;
    const int i0 = blockIdx.y * 8;
    const int tid = threadIdx.x;

    // stage W_ih block transposed: Wsm[k][c] = W_ih[(c0+c)*DG + k]
#pragma unroll
    for (int it = 0; it < 32; ++it) {
        int idx = tid + it * 64;             // 0..2047
        int c  = idx >> 5;                   // 0..63
        int k4 = (idx & 31) * 4;             // 0..124
        float4 v = *(const float4*)(W_ih + (size_t)(c0 + c) * DG + k4);
        Wsm[k4 + 0][c] = v.x; Wsm[k4 + 1][c] = v.y;
        Wsm[k4 + 2][c] = v.z; Wsm[k4 + 3][c] = v.w;
    }
    // stage msg row-pairs
#pragma unroll
    for (int it = 0; it < 8; ++it) {
        int idx = tid + it * 64;             // 0..511
        int rp = idx >> 7;                   // 0..3
        int k  = idx & 127;
        float lo = g_msg[(size_t)(i0 + 2 * rp)     * DG + k];
        float hi = g_msg[(size_t)(i0 + 2 * rp + 1) * DG + k];
        Apk[rp][k] = pk2(lo, hi);
    }
    __syncthreads();

    const int w    = tid >> 5;               // col-block
    const int lane = tid & 31;
    const int rp   = lane >> 3;
    const int cg   = lane & 7;
    const int cb   = w * 32 + cg * 4;

    u64 acc[4] = {0ull, 0ull, 0ull, 0ull};
#pragma unroll 4
    for (int k = 0; k < DG; ++k) {
        u64 a = Apk[rp][k];
        float w0 = Wsm[k][cb + 0];
        float w1 = Wsm[k][cb + 1];
        float w2 = Wsm[k][cb + 2];
        float w3 = Wsm[k][cb + 3];
        fma2(acc[0], a, pk2(w0, w0));
        fma2(acc[1], a, pk2(w1, w1));
        fma2(acc[2], a, pk2(w2, w2));
        fma2(acc[3], a, pk2(w3, w3));
    }

    const int r0 = i0 + 2 * rp;
#pragma unroll
    for (int q = 0; q < 4; ++q) {
        float2 f = upk(acc[q]);
        int col = c0 + cb + q;
        float bv = b_ih[col];
        g_gi[(size_t)r0 * 384 + col]       = f.x + bv;
        g_gi[(size_t)(r0 + 1) * 384 + col] = f.y + bv;
    }
}

// ============================================================
// GRU elementwise:  out = (1-z)*n + z*h
// ============================================================
__global__ __launch_bounds__(256) void gru_kernel(const float* __restrict__ X,
                                                  float* __restrict__ out)
{
    int idx = blockIdx.x * 256 + threadIdx.x;   // 0..131071
    int i = idx >> 7;
    int d = idx & 127;
    const float* gi = g_gi + (size_t)i * 384;
    const float* gh = g_gh + (size_t)i * 384;
    float r = 1.f / (1.f + __expf(-(gi[d] + gh[d])));
    float z = 1.f / (1.f + __expf(-(gi[128 + d] + gh[128 + d])));
    float n = tanhf(gi[256 + d] + r * gh[256 + d]);
    float hprev = X[idx];
    out[idx] = (1.f - z) * n + z * hprev;
}

// ============================================================
extern "C" void kernel_launch(void* const* d_in, const int* in_sizes, int n_in,
                              void* d_out, int out_size)
{
    (void)in_sizes; (void)n_in; (void)out_size;
    const float* X    = (const float*)d_in[0];   // [1024,128]
    const int*   adj  = (const int*)  d_in[1];   // [1024,1024]
    const float* W1   = (const float*)d_in[2];   // [256,256]
    const float* b1   = (const float*)d_in[3];   // [256]
    const float* W2   = (const float*)d_in[4];   // [128,256]
    const float* b2   = (const float*)d_in[5];   // [128]
    const float* W_ih = (const float*)d_in[6];   // [384,128]
    const float* W_hh = (const float*)d_in[7];   // [384,128]
    const float* b_ih = (const float*)d_in[8];   // [384]
    const float* b_hh = (const float*)d_in[9];   // [384]
    float* out = (float*)d_out;

    float *src, *nbr, *gh;
    cudaGetSymbolAddress((void**)&src, g_src);
    cudaGetSymbolAddress((void**)&nbr, g_nbr);
    cudaGetSymbolAddress((void**)&gh,  g_gh);

    // 1) src | nbr | gh in one launch (224 CTAs) — R3-proven
    gemm_fusedX_kernel<<<dim3(14, NG / 64), 256>>>(X, W1, b1, W_hh, b_hh, src, nbr, gh);
    // 2) masked relu aggregation -> 8 partial slabs + deg partials — R3-proven
    agg_part_kernel<<<dim3(NG / 8, JCH), 256>>>(adj);
    // 3) fold partials -> g_agg, g_deg — R3-proven
    agg_reduce_kernel<<<(NG * HG / 4) / 256, 256>>>();
    // 4) msg = agg @ W2^T + deg*b2   (smem-resident W, no shuffles; 512 CTAs)
    msg_tile_kernel<<<dim3(DG / 32, NG / 8), 64>>>(W2, b2);
    // 5) gi = msg @ W_ih^T + b_ih    (smem-resident W, no shuffles; 768 CTAs)
    gi_tile_kernel<<<dim3(384 / 64, NG / 8), 64>>>(W_ih, b_ih);
    // 6) GRU gates + output
    gru_kernel<<<(NG * DG) / 256, 256>>>(X, out);
}